// round 15
// baseline (speedup 1.0000x reference)
#include <cuda_runtime.h>
#include <cuda_fp16.h>
#include <cstdint>

#define DD 128
#define MAXN 100000
#define MAXE 1000000
#define NBLK_E 1184
#define TPB_E 256
#define WPB 8
#define BN_EPS 1e-5f

// ---------------- device scratch (no allocation allowed) ----------------
// +128 rows padding: gemm tail block stores full 16-row fragments
__device__ __half g_u[(MAXN + 128) * DD];        // node proj, u-half
__device__ __half g_v[(MAXN + 128) * DD];        // node proj, v-half
__device__ __align__(16) __half g_w1f[8 * 32 * 32 * 4]; // W1 in B-fragment layout
__device__ int2  g_ei32[MAXE];                   // edge index as int32 (8 MB)
__device__ __align__(16) float g_part[NBLK_E * 256]; // partials [block][feat]
__device__ float g_a[DD];                        // BN scale
__device__ float g_c[DD];                        // BN shift
__device__ unsigned g_bcount;                    // stats completion ticket (self-resets)

__device__ __forceinline__ uint32_t smem_u32(const void* p) {
    uint32_t a;
    asm("{ .reg .u64 t; cvta.to.shared.u64 t, %1; cvt.u32.u64 %0, t; }"
        : "=r"(a) : "l"(p));
    return a;
}

// ---------------- prep: W1 -> mma B-fragment layout | idx->int32 --------
// B frag (m16n8k16, col): lane l holds k={2c,2c+1,2c+8,2c+9}, n=l/4, c=l%4.
__global__ __launch_bounds__(256) void prep_kernel(
    const float* __restrict__ W1, const long long* __restrict__ ei, int E) {
    const int b = blockIdx.x;
    const int t = threadIdx.x;
    if (b < 128) {
        int idx = b * 256 + t;                   // 0..32767
        int o = idx >> 7, k = idx & 127;         // o: fused out 0..255, k: 0..127
        float val = (o < 128) ? W1[o * 256 + k] : W1[(o - 128) * 256 + 128 + k];
        int kt = k >> 4, k_in = k & 15;
        int ot = o >> 3, n_in = o & 7;
        int l = n_in * 4 + ((k_in & 7) >> 1);
        int slot = ((k_in >> 3) << 1) | (k_in & 1);
        g_w1f[(((kt * 32 + ot) * 32 + l) << 2) + slot] = __float2half(val);
    } else {
        // int64 edge_index (values < 2^31) has zero high dwords
        const int* eiv = (const int*)ei;
        int z = 0;
#pragma unroll
        for (int i = 0; i < 16; i++) z |= eiv[2 * i + 1];
        const bool is64 = (z == 0);
        int e = (b - 128) * 256 + t;
        if (e < E) {
            int2 o;
            if (is64) {
                longlong2 p = ((const longlong2*)ei)[e];
                o = make_int2((int)p.x, (int)p.y);
            } else {
                o = ((const int2*)ei)[e];
            }
            g_ei32[e] = o;
        }
    }
}

// ---------------- node GEMM: raw mma.sync, fb-outer for low reg pressure -
#define A_LD 136
#define GEMM_SMEM 34816
__global__ __launch_bounds__(256, 3) void node_gemm_mma_kernel(
    const float* __restrict__ x, int N) {
    extern __shared__ char raw[];
    __half (*As)[A_LD] = (__half(*)[A_LD])raw;   // [128][136]

    const int tid = threadIdx.x;
    const int warp = tid >> 5;
    const int lane = tid & 31;
    const int base = blockIdx.x * 128;
    const int wr = warp >> 1;
    const int wc = warp & 1;

    // Stage A: 128 nodes x 128 k, fp32 -> fp16 (4096 float4)
#pragma unroll
    for (int it = 0; it < 16; it++) {
        int idx = it * 256 + tid;
        int r = idx >> 5;
        int c4 = idx & 31;
        int node = base + r;
        float4 f = (node < N) ? ((const float4*)x)[node * 32 + c4]
                              : make_float4(0.f, 0.f, 0.f, 0.f);
        __half2 h0 = __floats2half2_rn(f.x, f.y);
        __half2 h1 = __floats2half2_rn(f.z, f.w);
        uint2 o;
        o.x = *(unsigned int*)&h0;
        o.y = *(unsigned int*)&h1;
        *(uint2*)&As[r][c4 * 4] = o;
    }
    __syncthreads();

    const uint32_t a_base = smem_u32(raw);
    const uint32_t rowptr = a_base +
        ((uint32_t)((wr * 32 + (lane & 15)) * A_LD + ((lane >> 4) << 3)) << 1);

    const uint2* __restrict__ Wf = (const uint2*)g_w1f;
    const int ot_base0 = wc * 8;
    const int row0 = base + wr * 32 + (lane >> 2);
    const int col0 = wc * 64 + ((lane & 3) << 1);

    for (int fb = 0; fb < 2; fb++) {
        uint32_t acc[2][8][2];
#pragma unroll
        for (int mt = 0; mt < 2; mt++)
#pragma unroll
            for (int nt = 0; nt < 8; nt++) {
                acc[mt][nt][0] = 0u;
                acc[mt][nt][1] = 0u;
            }

#pragma unroll
        for (int kt = 0; kt < 8; kt++) {
            uint32_t a[2][4];
#pragma unroll
            for (int mt = 0; mt < 2; mt++) {
                uint32_t addr = rowptr + (uint32_t)(mt * 16 * A_LD * 2 + kt * 32);
                asm volatile(
                    "ldmatrix.sync.aligned.m8n8.x4.shared.b16 {%0,%1,%2,%3}, [%4];"
                    : "=r"(a[mt][0]), "=r"(a[mt][1]), "=r"(a[mt][2]), "=r"(a[mt][3])
                    : "r"(addr));
            }
            uint2 bfr[8];
#pragma unroll
            for (int nt = 0; nt < 8; nt++)
                bfr[nt] = Wf[((kt * 32 + fb * 16 + ot_base0 + nt) << 5) + lane];
#pragma unroll
            for (int mt = 0; mt < 2; mt++)
#pragma unroll
                for (int nt = 0; nt < 8; nt++)
                    asm volatile(
                        "mma.sync.aligned.m16n8k16.row.col.f16.f16.f16.f16 "
                        "{%0,%1}, {%2,%3,%4,%5}, {%6,%7}, {%0,%1};"
                        : "+r"(acc[mt][nt][0]), "+r"(acc[mt][nt][1])
                        : "r"(a[mt][0]), "r"(a[mt][1]), "r"(a[mt][2]), "r"(a[mt][3]),
                          "r"(bfr[nt].x), "r"(bfr[nt].y));
        }

        __half* dst = fb ? g_v : g_u;
#pragma unroll
        for (int mt = 0; mt < 2; mt++)
#pragma unroll
            for (int nt = 0; nt < 8; nt++) {
                int r = row0 + mt * 16;
                int cc = col0 + nt * 8;
                *(uint32_t*)&dst[(unsigned)r * 128 + cc] = acc[mt][nt][0];
                *(uint32_t*)&dst[(unsigned)(r + 8) * 128 + cc] = acc[mt][nt][1];
            }
    }
}

// ---------------- edge pass 1: stats + last-block reduce/finalize -------
__global__ __launch_bounds__(TPB_E) void edge_stats_kernel(
    const float* __restrict__ gamma, const float* __restrict__ beta,
    float invE, int E, int stride) {
    const int lane = threadIdx.x & 31;
    const int hl = lane & 15;
    const int half = lane >> 4;
    const int wid = threadIdx.x >> 5;
    const int gw = blockIdx.x * WPB + wid;

    float s[8], q[8];
#pragma unroll
    for (int j = 0; j < 8; j++) { s[j] = 0.f; q[j] = 0.f; }

    const uint4* __restrict__ U = (const uint4*)g_u;
    const uint4* __restrict__ V = (const uint4*)g_v;
    const int4* __restrict__ EI = (const int4*)g_ei32;

#pragma unroll 4
    for (int it = gw * 2; it < E; it += stride) {
        int4 idx = EI[it >> 1];
        int src = half ? idx.z : idx.x;
        int dst = half ? idx.w : idx.y;
        uint4 ur = U[src * 16 + hl];
        uint4 vr = V[dst * 16 + hl];
        float2 u0 = __half22float2(*(__half2*)&ur.x);
        float2 u1 = __half22float2(*(__half2*)&ur.y);
        float2 u2 = __half22float2(*(__half2*)&ur.z);
        float2 u3 = __half22float2(*(__half2*)&ur.w);
        float2 v0 = __half22float2(*(__half2*)&vr.x);
        float2 v1 = __half22float2(*(__half2*)&vr.y);
        float2 v2 = __half22float2(*(__half2*)&vr.z);
        float2 v3 = __half22float2(*(__half2*)&vr.w);
        float w[8];
        w[0] = u0.x + v0.x; w[1] = u0.y + v0.y;
        w[2] = u1.x + v1.x; w[3] = u1.y + v1.y;
        w[4] = u2.x + v2.x; w[5] = u2.y + v2.y;
        w[6] = u3.x + v3.x; w[7] = u3.y + v3.y;
#pragma unroll
        for (int j = 0; j < 8; j++) {
            s[j] += w[j];
            q[j] = fmaf(w[j], w[j], q[j]);
        }
    }

    __shared__ float red[WPB * 256];
    float* r = red + wid * 256;
    if (half == 0) {
#pragma unroll
        for (int j = 0; j < 8; j++) { r[hl * 8 + j] = s[j]; r[128 + hl * 8 + j] = q[j]; }
    }
    __syncwarp();
    if (half == 1) {
#pragma unroll
        for (int j = 0; j < 8; j++) { r[hl * 8 + j] += s[j]; r[128 + hl * 8 + j] += q[j]; }
    }
    __syncthreads();
    const int j = threadIdx.x;
    float t = 0.f;
#pragma unroll
    for (int w = 0; w < WPB; w++) t += red[w * 256 + j];
    g_part[blockIdx.x * 256 + j] = t;            // [block][feat], coalesced

    // ---- ticket: last block reduces all partials and finalizes BN ----
    __shared__ bool isLast;
    __threadfence();
    __syncthreads();
    if (j == 0) {
        unsigned tk = atomicAdd(&g_bcount, 1u);
        isLast = (tk == (unsigned)(gridDim.x - 1));
    }
    __syncthreads();
    if (!isLast) return;

    // last block: 4-way sliced, float4-vectorized reduction of [1184][256]
    const int fg = j & 63;                       // feature group (4 floats)
    const int slice = j >> 6;                    // block-range slice 0..3
    const float4* __restrict__ P = (const float4*)g_part;  // [1184][64]
    float4 a4 = make_float4(0.f, 0.f, 0.f, 0.f);
    for (int b = slice; b < NBLK_E; b += 4) {
        float4 p = P[b * 64 + fg];
        a4.x += p.x; a4.y += p.y; a4.z += p.z; a4.w += p.w;
    }
    float4* sm4 = (float4*)red;                  // reuse smem
    sm4[j] = a4;
    __syncthreads();
    float* smf = red + 1024;                     // flat 256 totals
    if (j < 64) {
        float4 t0 = sm4[j], t1 = sm4[64 + j], t2 = sm4[128 + j], t3 = sm4[192 + j];
        smf[j * 4 + 0] = t0.x + t1.x + t2.x + t3.x;
        smf[j * 4 + 1] = t0.y + t1.y + t2.y + t3.y;
        smf[j * 4 + 2] = t0.z + t1.z + t2.z + t3.z;
        smf[j * 4 + 3] = t0.w + t1.w + t2.w + t3.w;
    }
    __syncthreads();
    if (j < 128) {
        float mean = smf[j] * invE;
        float var = fmaf(-mean, mean, smf[128 + j] * invE);
        float a = gamma[j] * rsqrtf(var + BN_EPS);
        g_a[j] = a;
        g_c[j] = fmaf(-a, mean, beta[j]);
    }
    if (j == 0) g_bcount = 0;                    // reset for next replay
}

// ---------------- edge pass 2: out. 16 lanes/edge, 2 edges/warp ---------
__global__ __launch_bounds__(TPB_E) void edge_out_kernel(
    const float* __restrict__ W2, const float* __restrict__ b2,
    float* __restrict__ out, int E, int stride) {
    const int lane = threadIdx.x & 31;
    const int hl = lane & 15;
    const int half = lane >> 4;
    const int gw = blockIdx.x * WPB + (threadIdx.x >> 5);

    float a[8], c[8], wa[8], wb[8];
    {
        float4 t0 = *(const float4*)&g_a[hl * 8];
        float4 t1 = *(const float4*)&g_a[hl * 8 + 4];
        a[0]=t0.x; a[1]=t0.y; a[2]=t0.z; a[3]=t0.w;
        a[4]=t1.x; a[5]=t1.y; a[6]=t1.z; a[7]=t1.w;
        t0 = *(const float4*)&g_c[hl * 8];
        t1 = *(const float4*)&g_c[hl * 8 + 4];
        c[0]=t0.x; c[1]=t0.y; c[2]=t0.z; c[3]=t0.w;
        c[4]=t1.x; c[5]=t1.y; c[6]=t1.z; c[7]=t1.w;
        t0 = *(const float4*)&W2[hl * 8];
        t1 = *(const float4*)&W2[hl * 8 + 4];
        wa[0]=t0.x; wa[1]=t0.y; wa[2]=t0.z; wa[3]=t0.w;
        wa[4]=t1.x; wa[5]=t1.y; wa[6]=t1.z; wa[7]=t1.w;
        t0 = *(const float4*)&W2[128 + hl * 8];
        t1 = *(const float4*)&W2[128 + hl * 8 + 4];
        wb[0]=t0.x; wb[1]=t0.y; wb[2]=t0.z; wb[3]=t0.w;
        wb[4]=t1.x; wb[5]=t1.y; wb[6]=t1.z; wb[7]=t1.w;
    }
    const float bz0 = b2[0], bz1 = b2[1];

    const uint4* __restrict__ U = (const uint4*)g_u;
    const uint4* __restrict__ V = (const uint4*)g_v;
    const int4* __restrict__ EI = (const int4*)g_ei32;

#pragma unroll 4
    for (int it = gw * 2; it < E; it += stride) {
        int4 idx = EI[it >> 1];
        int src = half ? idx.z : idx.x;
        int dst = half ? idx.w : idx.y;
        uint4 ur = U[src * 16 + hl];
        uint4 vr = V[dst * 16 + hl];
        float2 u0 = __half22float2(*(__half2*)&ur.x);
        float2 u1 = __half22float2(*(__half2*)&ur.y);
        float2 u2 = __half22float2(*(__half2*)&ur.z);
        float2 u3 = __half22float2(*(__half2*)&ur.w);
        float2 v0 = __half22float2(*(__half2*)&vr.x);
        float2 v1 = __half22float2(*(__half2*)&vr.y);
        float2 v2 = __half22float2(*(__half2*)&vr.z);
        float2 v3 = __half22float2(*(__half2*)&vr.w);
        float w[8];
        w[0] = u0.x + v0.x; w[1] = u0.y + v0.y;
        w[2] = u1.x + v1.x; w[3] = u1.y + v1.y;
        w[4] = u2.x + v2.x; w[5] = u2.y + v2.y;
        w[6] = u3.x + v3.x; w[7] = u3.y + v3.y;
        float p0 = 0.f, p1 = 0.f;
#pragma unroll
        for (int j = 0; j < 8; j++) {
            float rr = fmaxf(fmaf(a[j], w[j], c[j]), 0.f);
            p0 = fmaf(rr, wa[j], p0);
            p1 = fmaf(rr, wb[j], p1);
        }
#pragma unroll
        for (int o = 8; o > 0; o >>= 1) {
            p0 += __shfl_xor_sync(0xFFFFFFFFu, p0, o);
            p1 += __shfl_xor_sync(0xFFFFFFFFu, p1, o);
        }
        if (hl == 0)
            ((float2*)out)[it + half] = make_float2(p0 + bz0, p1 + bz1);
    }
}

// ---------------- launch ------------------------------------------------
extern "C" void kernel_launch(void* const* d_in, const int* in_sizes, int n_in,
                              void* d_out, int out_size) {
    const float* x = (const float*)d_in[0];
    const long long* ei = (const long long*)d_in[1];
    const float* W1 = (const float*)d_in[2];
    // d_in[3] = b1 : cancels inside BatchNorm, unused
    const float* gamma = (const float*)d_in[4];
    const float* beta = (const float*)d_in[5];
    const float* W2 = (const float*)d_in[6];
    const float* b2 = (const float*)d_in[7];

    const int N = in_sizes[0] / DD;
    const int E = in_sizes[1] / 2;
    const int stride = NBLK_E * WPB * 2;
    const int eb = (E + 255) / 256;

    static int smem_set = 0;
    if (!smem_set) {
        cudaFuncSetAttribute(node_gemm_mma_kernel,
                             cudaFuncAttributeMaxDynamicSharedMemorySize, GEMM_SMEM);
        smem_set = 1;
    }

    prep_kernel<<<128 + eb, 256>>>(W1, ei, E);
    node_gemm_mma_kernel<<<(N + 127) / 128, 256, GEMM_SMEM>>>(x, N);
    edge_stats_kernel<<<NBLK_E, TPB_E>>>(gamma, beta, 1.0f / (float)E, E, stride);
    edge_out_kernel<<<NBLK_E, TPB_E>>>(W2, b2, (float*)d_out, E, stride);
}

// round 16
// speedup vs baseline: 1.2735x; 1.2735x over previous
#include <cuda_runtime.h>
#include <cuda_fp16.h>
#include <cstdint>

#define DD 128
#define MAXN 100000
#define MAXE 1000000
#define NBLK_E 1184
#define TPB_E 256
#define WPB 8
#define BN_EPS 1e-5f

// ---------------- device scratch (no allocation allowed) ----------------
// +128 rows padding: gemm tail block stores full 16-row fragments
__device__ __half g_u[(MAXN + 128) * DD];        // node proj, u-half
__device__ __half g_v[(MAXN + 128) * DD];        // node proj, v-half
__device__ __align__(16) __half g_w1f[8 * 32 * 32 * 4]; // W1 in B-fragment layout
__device__ int2  g_ei32[MAXE];                   // edge index as int32 (8 MB)
__device__ float g_part[256 * NBLK_E];           // transposed partials [feat][block]
__device__ float g_a[DD];                        // BN scale
__device__ float g_c[DD];                        // BN shift

__device__ __forceinline__ uint32_t smem_u32(const void* p) {
    uint32_t a;
    asm("{ .reg .u64 t; cvta.to.shared.u64 t, %1; cvt.u32.u64 %0, t; }"
        : "=r"(a) : "l"(p));
    return a;
}

// ---------------- prep: W1 -> mma B-fragment layout | idx->int32 --------
// B frag (m16n8k16, col): lane l holds k={2c,2c+1,2c+8,2c+9}, n=l/4, c=l%4.
__global__ __launch_bounds__(256) void prep_kernel(
    const float* __restrict__ W1, const long long* __restrict__ ei, int E) {
    const int b = blockIdx.x;
    const int t = threadIdx.x;
    if (b < 128) {
        int idx = b * 256 + t;                   // 0..32767
        int o = idx >> 7, k = idx & 127;         // o: fused out 0..255, k: 0..127
        float val = (o < 128) ? W1[o * 256 + k] : W1[(o - 128) * 256 + 128 + k];
        int kt = k >> 4, k_in = k & 15;
        int ot = o >> 3, n_in = o & 7;
        int l = n_in * 4 + ((k_in & 7) >> 1);
        int slot = ((k_in >> 3) << 1) | (k_in & 1);
        g_w1f[(((kt * 32 + ot) * 32 + l) << 2) + slot] = __float2half(val);
    } else {
        // int64 edge_index (values < 2^31) has zero high dwords
        const int* eiv = (const int*)ei;
        int z = 0;
#pragma unroll
        for (int i = 0; i < 16; i++) z |= eiv[2 * i + 1];
        const bool is64 = (z == 0);
        int e = (b - 128) * 256 + t;
        if (e < E) {
            int2 o;
            if (is64) {
                longlong2 p = ((const longlong2*)ei)[e];
                o = make_int2((int)p.x, (int)p.y);
            } else {
                o = ((const int2*)ei)[e];
            }
            g_ei32[e] = o;
        }
    }
}

// ---------------- node GEMM: raw mma.sync, fb-outer for low reg pressure -
#define A_LD 136
#define GEMM_SMEM 34816
__global__ __launch_bounds__(256, 3) void node_gemm_mma_kernel(
    const float* __restrict__ x, int N) {
    extern __shared__ char raw[];
    __half (*As)[A_LD] = (__half(*)[A_LD])raw;   // [128][136]

    const int tid = threadIdx.x;
    const int warp = tid >> 5;
    const int lane = tid & 31;
    const int base = blockIdx.x * 128;
    const int wr = warp >> 1;
    const int wc = warp & 1;

    // Stage A: 128 nodes x 128 k, fp32 -> fp16 (4096 float4)
#pragma unroll
    for (int it = 0; it < 16; it++) {
        int idx = it * 256 + tid;
        int r = idx >> 5;
        int c4 = idx & 31;
        int node = base + r;
        float4 f = (node < N) ? ((const float4*)x)[node * 32 + c4]
                              : make_float4(0.f, 0.f, 0.f, 0.f);
        __half2 h0 = __floats2half2_rn(f.x, f.y);
        __half2 h1 = __floats2half2_rn(f.z, f.w);
        uint2 o;
        o.x = *(unsigned int*)&h0;
        o.y = *(unsigned int*)&h1;
        *(uint2*)&As[r][c4 * 4] = o;
    }
    __syncthreads();

    const uint32_t a_base = smem_u32(raw);
    const uint32_t rowptr = a_base +
        ((uint32_t)((wr * 32 + (lane & 15)) * A_LD + ((lane >> 4) << 3)) << 1);

    const uint2* __restrict__ Wf = (const uint2*)g_w1f;
    const int ot_base0 = wc * 8;
    const int row0 = base + wr * 32 + (lane >> 2);
    const int col0 = wc * 64 + ((lane & 3) << 1);

    for (int fb = 0; fb < 2; fb++) {
        uint32_t acc[2][8][2];
#pragma unroll
        for (int mt = 0; mt < 2; mt++)
#pragma unroll
            for (int nt = 0; nt < 8; nt++) {
                acc[mt][nt][0] = 0u;
                acc[mt][nt][1] = 0u;
            }

#pragma unroll
        for (int kt = 0; kt < 8; kt++) {
            uint32_t a[2][4];
#pragma unroll
            for (int mt = 0; mt < 2; mt++) {
                uint32_t addr = rowptr + (uint32_t)(mt * 16 * A_LD * 2 + kt * 32);
                asm volatile(
                    "ldmatrix.sync.aligned.m8n8.x4.shared.b16 {%0,%1,%2,%3}, [%4];"
                    : "=r"(a[mt][0]), "=r"(a[mt][1]), "=r"(a[mt][2]), "=r"(a[mt][3])
                    : "r"(addr));
            }
            uint2 bfr[8];
#pragma unroll
            for (int nt = 0; nt < 8; nt++)
                bfr[nt] = Wf[((kt * 32 + fb * 16 + ot_base0 + nt) << 5) + lane];
#pragma unroll
            for (int mt = 0; mt < 2; mt++)
#pragma unroll
                for (int nt = 0; nt < 8; nt++)
                    asm volatile(
                        "mma.sync.aligned.m16n8k16.row.col.f16.f16.f16.f16 "
                        "{%0,%1}, {%2,%3,%4,%5}, {%6,%7}, {%0,%1};"
                        : "+r"(acc[mt][nt][0]), "+r"(acc[mt][nt][1])
                        : "r"(a[mt][0]), "r"(a[mt][1]), "r"(a[mt][2]), "r"(a[mt][3]),
                          "r"(bfr[nt].x), "r"(bfr[nt].y));
        }

        __half* dst = fb ? g_v : g_u;
#pragma unroll
        for (int mt = 0; mt < 2; mt++)
#pragma unroll
            for (int nt = 0; nt < 8; nt++) {
                int r = row0 + mt * 16;
                int cc = col0 + nt * 8;
                *(uint32_t*)&dst[(unsigned)r * 128 + cc] = acc[mt][nt][0];
                *(uint32_t*)&dst[(unsigned)(r + 8) * 128 + cc] = acc[mt][nt][1];
            }
    }
}

// ---------------- edge pass 1: stats. 16 lanes/edge, 2 edges/warp -------
// (R14 form exactly — register/occupancy fragile, do not touch)
__global__ __launch_bounds__(TPB_E) void edge_stats_kernel(int E, int stride) {
    const int lane = threadIdx.x & 31;
    const int hl = lane & 15;
    const int half = lane >> 4;
    const int wid = threadIdx.x >> 5;
    const int gw = blockIdx.x * WPB + wid;

    float s[8], q[8];
#pragma unroll
    for (int j = 0; j < 8; j++) { s[j] = 0.f; q[j] = 0.f; }

    const uint4* __restrict__ U = (const uint4*)g_u;
    const uint4* __restrict__ V = (const uint4*)g_v;
    const int4* __restrict__ EI = (const int4*)g_ei32;

#pragma unroll 4
    for (int it = gw * 2; it < E; it += stride) {
        int4 idx = EI[it >> 1];
        int src = half ? idx.z : idx.x;
        int dst = half ? idx.w : idx.y;
        uint4 ur = U[src * 16 + hl];
        uint4 vr = V[dst * 16 + hl];
        float2 u0 = __half22float2(*(__half2*)&ur.x);
        float2 u1 = __half22float2(*(__half2*)&ur.y);
        float2 u2 = __half22float2(*(__half2*)&ur.z);
        float2 u3 = __half22float2(*(__half2*)&ur.w);
        float2 v0 = __half22float2(*(__half2*)&vr.x);
        float2 v1 = __half22float2(*(__half2*)&vr.y);
        float2 v2 = __half22float2(*(__half2*)&vr.z);
        float2 v3 = __half22float2(*(__half2*)&vr.w);
        float w[8];
        w[0] = u0.x + v0.x; w[1] = u0.y + v0.y;
        w[2] = u1.x + v1.x; w[3] = u1.y + v1.y;
        w[4] = u2.x + v2.x; w[5] = u2.y + v2.y;
        w[6] = u3.x + v3.x; w[7] = u3.y + v3.y;
#pragma unroll
        for (int j = 0; j < 8; j++) {
            s[j] += w[j];
            q[j] = fmaf(w[j], w[j], q[j]);
        }
    }

    __shared__ float red[WPB * 256];
    float* r = red + wid * 256;
    if (half == 0) {
#pragma unroll
        for (int j = 0; j < 8; j++) { r[hl * 8 + j] = s[j]; r[128 + hl * 8 + j] = q[j]; }
    }
    __syncwarp();
    if (half == 1) {
#pragma unroll
        for (int j = 0; j < 8; j++) { r[hl * 8 + j] += s[j]; r[128 + hl * 8 + j] += q[j]; }
    }
    __syncthreads();
    int j = threadIdx.x;
    float t = 0.f;
#pragma unroll
    for (int w = 0; w < WPB; w++) t += red[w * 256 + j];
    g_part[j * NBLK_E + blockIdx.x] = t;
}

// ---------------- fused reduce + BN finalize: 128 blocks ----------------
__global__ __launch_bounds__(256) void reduce_finalize_kernel(
    const float* __restrict__ gamma, const float* __restrict__ beta,
    float invE) {
    const int j = blockIdx.x;
    const int t = threadIdx.x;
    float s = 0.f, q = 0.f;
    for (int b = t; b < NBLK_E; b += 256) {
        s += g_part[j * NBLK_E + b];
        q += g_part[(128 + j) * NBLK_E + b];
    }
    __shared__ float rs[256], rq[256];
    rs[t] = s; rq[t] = q;
    __syncthreads();
#pragma unroll
    for (int o = 128; o >= 32; o >>= 1) {
        if (t < o) { rs[t] += rs[t + o]; rq[t] += rq[t + o]; }
        __syncthreads();
    }
    if (t < 32) {
        float vs = rs[t], vq = rq[t];
#pragma unroll
        for (int o = 16; o > 0; o >>= 1) {
            vs += __shfl_xor_sync(0xFFFFFFFFu, vs, o);
            vq += __shfl_xor_sync(0xFFFFFFFFu, vq, o);
        }
        if (t == 0) {
            float mean = vs * invE;
            float var = fmaf(-mean, mean, vq * invE);
            float a = gamma[j] * rsqrtf(var + BN_EPS);
            g_a[j] = a;
            g_c[j] = fmaf(-a, mean, beta[j]);
        }
    }
}

// ---------------- edge pass 2: out. w=u+v in fp16 (HADD2) ---------------
__global__ __launch_bounds__(TPB_E) void edge_out_kernel(
    const float* __restrict__ W2, const float* __restrict__ b2,
    float* __restrict__ out, int E, int stride) {
    const int lane = threadIdx.x & 31;
    const int hl = lane & 15;
    const int half = lane >> 4;
    const int gw = blockIdx.x * WPB + (threadIdx.x >> 5);

    float a[8], c[8], wa[8], wb[8];
    {
        float4 t0 = *(const float4*)&g_a[hl * 8];
        float4 t1 = *(const float4*)&g_a[hl * 8 + 4];
        a[0]=t0.x; a[1]=t0.y; a[2]=t0.z; a[3]=t0.w;
        a[4]=t1.x; a[5]=t1.y; a[6]=t1.z; a[7]=t1.w;
        t0 = *(const float4*)&g_c[hl * 8];
        t1 = *(const float4*)&g_c[hl * 8 + 4];
        c[0]=t0.x; c[1]=t0.y; c[2]=t0.z; c[3]=t0.w;
        c[4]=t1.x; c[5]=t1.y; c[6]=t1.z; c[7]=t1.w;
        t0 = *(const float4*)&W2[hl * 8];
        t1 = *(const float4*)&W2[hl * 8 + 4];
        wa[0]=t0.x; wa[1]=t0.y; wa[2]=t0.z; wa[3]=t0.w;
        wa[4]=t1.x; wa[5]=t1.y; wa[6]=t1.z; wa[7]=t1.w;
        t0 = *(const float4*)&W2[128 + hl * 8];
        t1 = *(const float4*)&W2[128 + hl * 8 + 4];
        wb[0]=t0.x; wb[1]=t0.y; wb[2]=t0.z; wb[3]=t0.w;
        wb[4]=t1.x; wb[5]=t1.y; wb[6]=t1.z; wb[7]=t1.w;
    }
    const float bz0 = b2[0], bz1 = b2[1];

    const uint4* __restrict__ U = (const uint4*)g_u;
    const uint4* __restrict__ V = (const uint4*)g_v;
    const int4* __restrict__ EI = (const int4*)g_ei32;

#pragma unroll 4
    for (int it = gw * 2; it < E; it += stride) {
        int4 idx = EI[it >> 1];
        int src = half ? idx.z : idx.x;
        int dst = half ? idx.w : idx.y;
        uint4 ur = U[src * 16 + hl];
        uint4 vr = V[dst * 16 + hl];
        // w = u + v in fp16 domain: 4 HADD2 instead of 16 cvt + 8 fadd
        __half2 w01 = __hadd2(*(__half2*)&ur.x, *(__half2*)&vr.x);
        __half2 w23 = __hadd2(*(__half2*)&ur.y, *(__half2*)&vr.y);
        __half2 w45 = __hadd2(*(__half2*)&ur.z, *(__half2*)&vr.z);
        __half2 w67 = __hadd2(*(__half2*)&ur.w, *(__half2*)&vr.w);
        float2 f0 = __half22float2(w01);
        float2 f1 = __half22float2(w23);
        float2 f2 = __half22float2(w45);
        float2 f3 = __half22float2(w67);
        float w[8] = {f0.x, f0.y, f1.x, f1.y, f2.x, f2.y, f3.x, f3.y};
        float p0 = 0.f, p1 = 0.f;
#pragma unroll
        for (int j = 0; j < 8; j++) {
            float rr = fmaxf(fmaf(a[j], w[j], c[j]), 0.f);
            p0 = fmaf(rr, wa[j], p0);
            p1 = fmaf(rr, wb[j], p1);
        }
#pragma unroll
        for (int o = 8; o > 0; o >>= 1) {
            p0 += __shfl_xor_sync(0xFFFFFFFFu, p0, o);
            p1 += __shfl_xor_sync(0xFFFFFFFFu, p1, o);
        }
        if (hl == 0)
            ((float2*)out)[it + half] = make_float2(p0 + bz0, p1 + bz1);
    }
}

// ---------------- launch ------------------------------------------------
extern "C" void kernel_launch(void* const* d_in, const int* in_sizes, int n_in,
                              void* d_out, int out_size) {
    const float* x = (const float*)d_in[0];
    const long long* ei = (const long long*)d_in[1];
    const float* W1 = (const float*)d_in[2];
    // d_in[3] = b1 : cancels inside BatchNorm, unused
    const float* gamma = (const float*)d_in[4];
    const float* beta = (const float*)d_in[5];
    const float* W2 = (const float*)d_in[6];
    const float* b2 = (const float*)d_in[7];

    const int N = in_sizes[0] / DD;
    const int E = in_sizes[1] / 2;
    const int stride = NBLK_E * WPB * 2;
    const int eb = (E + 255) / 256;

    static int smem_set = 0;
    if (!smem_set) {
        cudaFuncSetAttribute(node_gemm_mma_kernel,
                             cudaFuncAttributeMaxDynamicSharedMemorySize, GEMM_SMEM);
        smem_set = 1;
    }

    prep_kernel<<<128 + eb, 256>>>(W1, ei, E);
    node_gemm_mma_kernel<<<(N + 127) / 128, 256, GEMM_SMEM>>>(x, N);
    edge_stats_kernel<<<NBLK_E, TPB_E>>>(E, stride);
    reduce_finalize_kernel<<<128, 256>>>(gamma, beta, 1.0f / (float)E);
    edge_out_kernel<<<NBLK_E, TPB_E>>>(W2, b2, (float*)d_out, E, stride);
}

// round 17
// speedup vs baseline: 1.2870x; 1.0106x over previous
#include <cuda_runtime.h>
#include <cuda_fp16.h>
#include <cstdint>

#define DD 128
#define MAXN 100000
#define MAXE 1000000
#define NBLK_E 1184
#define TPB_E 256
#define WPB 8
#define BN_EPS 1e-5f

// ---------------- device scratch (no allocation allowed) ----------------
// +128 rows padding: gemm tail block stores full 16-row fragments
__device__ __half g_u[(MAXN + 128) * DD];        // node proj, u-half
__device__ __half g_v[(MAXN + 128) * DD];        // node proj, v-half
__device__ __align__(16) __half g_w1f[8 * 32 * 32 * 4]; // W1 in B-fragment layout
__device__ int2  g_ei32[MAXE];                   // edge index as int32 (8 MB)
__device__ float g_part[256 * NBLK_E];           // transposed partials [feat][block]
__device__ float g_a[DD];                        // BN scale
__device__ float g_c[DD];                        // BN shift

__device__ __forceinline__ uint32_t smem_u32(const void* p) {
    uint32_t a;
    asm("{ .reg .u64 t; cvta.to.shared.u64 t, %1; cvt.u32.u64 %0, t; }"
        : "=r"(a) : "l"(p));
    return a;
}

// ---------------- prep: W1 -> mma B-fragment layout | idx->int32 --------
// B frag (m16n8k16, col): lane l holds k={2c,2c+1,2c+8,2c+9}, n=l/4, c=l%4.
__global__ __launch_bounds__(256) void prep_kernel(
    const float* __restrict__ W1, const long long* __restrict__ ei, int E) {
    const int b = blockIdx.x;
    const int t = threadIdx.x;
    if (b < 128) {
        int idx = b * 256 + t;                   // 0..32767
        int o = idx >> 7, k = idx & 127;         // o: fused out 0..255, k: 0..127
        float val = (o < 128) ? W1[o * 256 + k] : W1[(o - 128) * 256 + 128 + k];
        int kt = k >> 4, k_in = k & 15;
        int ot = o >> 3, n_in = o & 7;
        int l = n_in * 4 + ((k_in & 7) >> 1);
        int slot = ((k_in >> 3) << 1) | (k_in & 1);
        g_w1f[(((kt * 32 + ot) * 32 + l) << 2) + slot] = __float2half(val);
    } else {
        // int64 edge_index (values < 2^31) has zero high dwords
        const int* eiv = (const int*)ei;
        int z = 0;
#pragma unroll
        for (int i = 0; i < 16; i++) z |= eiv[2 * i + 1];
        const bool is64 = (z == 0);
        int e = (b - 128) * 256 + t;
        if (e < E) {
            int2 o;
            if (is64) {
                longlong2 p = ((const longlong2*)ei)[e];
                o = make_int2((int)p.x, (int)p.y);
            } else {
                o = ((const int2*)ei)[e];
            }
            g_ei32[e] = o;
        }
    }
}

// ---------------- node GEMM: raw mma.sync, fb-outer for low reg pressure -
#define A_LD 136
#define GEMM_SMEM 34816
__global__ __launch_bounds__(256, 3) void node_gemm_mma_kernel(
    const float* __restrict__ x, int N) {
    extern __shared__ char raw[];
    __half (*As)[A_LD] = (__half(*)[A_LD])raw;   // [128][136]

    const int tid = threadIdx.x;
    const int warp = tid >> 5;
    const int lane = tid & 31;
    const int base = blockIdx.x * 128;
    const int wr = warp >> 1;
    const int wc = warp & 1;

    // Stage A: 128 nodes x 128 k, fp32 -> fp16 (4096 float4)
#pragma unroll
    for (int it = 0; it < 16; it++) {
        int idx = it * 256 + tid;
        int r = idx >> 5;
        int c4 = idx & 31;
        int node = base + r;
        float4 f = (node < N) ? ((const float4*)x)[node * 32 + c4]
                              : make_float4(0.f, 0.f, 0.f, 0.f);
        __half2 h0 = __floats2half2_rn(f.x, f.y);
        __half2 h1 = __floats2half2_rn(f.z, f.w);
        uint2 o;
        o.x = *(unsigned int*)&h0;
        o.y = *(unsigned int*)&h1;
        *(uint2*)&As[r][c4 * 4] = o;
    }
    __syncthreads();

    const uint32_t a_base = smem_u32(raw);
    const uint32_t rowptr = a_base +
        ((uint32_t)((wr * 32 + (lane & 15)) * A_LD + ((lane >> 4) << 3)) << 1);

    const uint2* __restrict__ Wf = (const uint2*)g_w1f;
    const int ot_base0 = wc * 8;
    const int row0 = base + wr * 32 + (lane >> 2);
    const int col0 = wc * 64 + ((lane & 3) << 1);

    for (int fb = 0; fb < 2; fb++) {
        uint32_t acc[2][8][2];
#pragma unroll
        for (int mt = 0; mt < 2; mt++)
#pragma unroll
            for (int nt = 0; nt < 8; nt++) {
                acc[mt][nt][0] = 0u;
                acc[mt][nt][1] = 0u;
            }

#pragma unroll
        for (int kt = 0; kt < 8; kt++) {
            uint32_t a[2][4];
#pragma unroll
            for (int mt = 0; mt < 2; mt++) {
                uint32_t addr = rowptr + (uint32_t)(mt * 16 * A_LD * 2 + kt * 32);
                asm volatile(
                    "ldmatrix.sync.aligned.m8n8.x4.shared.b16 {%0,%1,%2,%3}, [%4];"
                    : "=r"(a[mt][0]), "=r"(a[mt][1]), "=r"(a[mt][2]), "=r"(a[mt][3])
                    : "r"(addr));
            }
            uint2 bfr[8];
#pragma unroll
            for (int nt = 0; nt < 8; nt++)
                bfr[nt] = Wf[((kt * 32 + fb * 16 + ot_base0 + nt) << 5) + lane];
#pragma unroll
            for (int mt = 0; mt < 2; mt++)
#pragma unroll
                for (int nt = 0; nt < 8; nt++)
                    asm volatile(
                        "mma.sync.aligned.m16n8k16.row.col.f16.f16.f16.f16 "
                        "{%0,%1}, {%2,%3,%4,%5}, {%6,%7}, {%0,%1};"
                        : "+r"(acc[mt][nt][0]), "+r"(acc[mt][nt][1])
                        : "r"(a[mt][0]), "r"(a[mt][1]), "r"(a[mt][2]), "r"(a[mt][3]),
                          "r"(bfr[nt].x), "r"(bfr[nt].y));
        }

        __half* dst = fb ? g_v : g_u;
#pragma unroll
        for (int mt = 0; mt < 2; mt++)
#pragma unroll
            for (int nt = 0; nt < 8; nt++) {
                int r = row0 + mt * 16;
                int cc = col0 + nt * 8;
                *(uint32_t*)&dst[(unsigned)r * 128 + cc] = acc[mt][nt][0];
                *(uint32_t*)&dst[(unsigned)(r + 8) * 128 + cc] = acc[mt][nt][1];
            }
    }
}

// ---------------- edge pass 1: stats. 16 lanes/edge, 2 edges/warp -------
// (R14 form exactly — register/occupancy fragile, do not touch)
__global__ __launch_bounds__(TPB_E) void edge_stats_kernel(int E, int stride) {
    const int lane = threadIdx.x & 31;
    const int hl = lane & 15;
    const int half = lane >> 4;
    const int wid = threadIdx.x >> 5;
    const int gw = blockIdx.x * WPB + wid;

    float s[8], q[8];
#pragma unroll
    for (int j = 0; j < 8; j++) { s[j] = 0.f; q[j] = 0.f; }

    const uint4* __restrict__ U = (const uint4*)g_u;
    const uint4* __restrict__ V = (const uint4*)g_v;
    const int4* __restrict__ EI = (const int4*)g_ei32;

#pragma unroll 4
    for (int it = gw * 2; it < E; it += stride) {
        int4 idx = EI[it >> 1];
        int src = half ? idx.z : idx.x;
        int dst = half ? idx.w : idx.y;
        uint4 ur = U[src * 16 + hl];
        uint4 vr = V[dst * 16 + hl];
        float2 u0 = __half22float2(*(__half2*)&ur.x);
        float2 u1 = __half22float2(*(__half2*)&ur.y);
        float2 u2 = __half22float2(*(__half2*)&ur.z);
        float2 u3 = __half22float2(*(__half2*)&ur.w);
        float2 v0 = __half22float2(*(__half2*)&vr.x);
        float2 v1 = __half22float2(*(__half2*)&vr.y);
        float2 v2 = __half22float2(*(__half2*)&vr.z);
        float2 v3 = __half22float2(*(__half2*)&vr.w);
        float w[8];
        w[0] = u0.x + v0.x; w[1] = u0.y + v0.y;
        w[2] = u1.x + v1.x; w[3] = u1.y + v1.y;
        w[4] = u2.x + v2.x; w[5] = u2.y + v2.y;
        w[6] = u3.x + v3.x; w[7] = u3.y + v3.y;
#pragma unroll
        for (int j = 0; j < 8; j++) {
            s[j] += w[j];
            q[j] = fmaf(w[j], w[j], q[j]);
        }
    }

    __shared__ float red[WPB * 256];
    float* r = red + wid * 256;
    if (half == 0) {
#pragma unroll
        for (int j = 0; j < 8; j++) { r[hl * 8 + j] = s[j]; r[128 + hl * 8 + j] = q[j]; }
    }
    __syncwarp();
    if (half == 1) {
#pragma unroll
        for (int j = 0; j < 8; j++) { r[hl * 8 + j] += s[j]; r[128 + hl * 8 + j] += q[j]; }
    }
    __syncthreads();
    int j = threadIdx.x;
    float t = 0.f;
#pragma unroll
    for (int w = 0; w < WPB; w++) t += red[w * 256 + j];
    g_part[j * NBLK_E + blockIdx.x] = t;
}

// ---------------- fused reduce + BN finalize: 128 blocks ----------------
__global__ __launch_bounds__(256) void reduce_finalize_kernel(
    const float* __restrict__ gamma, const float* __restrict__ beta,
    float invE) {
    const int j = blockIdx.x;
    const int t = threadIdx.x;
    float s = 0.f, q = 0.f;
    for (int b = t; b < NBLK_E; b += 256) {
        s += g_part[j * NBLK_E + b];
        q += g_part[(128 + j) * NBLK_E + b];
    }
    __shared__ float rs[256], rq[256];
    rs[t] = s; rq[t] = q;
    __syncthreads();
#pragma unroll
    for (int o = 128; o >= 32; o >>= 1) {
        if (t < o) { rs[t] += rs[t + o]; rq[t] += rq[t + o]; }
        __syncthreads();
    }
    if (t < 32) {
        float vs = rs[t], vq = rq[t];
#pragma unroll
        for (int o = 16; o > 0; o >>= 1) {
            vs += __shfl_xor_sync(0xFFFFFFFFu, vs, o);
            vq += __shfl_xor_sync(0xFFFFFFFFu, vq, o);
        }
        if (t == 0) {
            float mean = vs * invE;
            float var = fmaf(-mean, mean, vq * invE);
            float a = gamma[j] * rsqrtf(var + BN_EPS);
            g_a[j] = a;
            g_c[j] = fmaf(-a, mean, beta[j]);
        }
    }
}

// ---------------- edge pass 2: out. fp16 BN-ReLU (HFMA2/HMAX2) ----------
__global__ __launch_bounds__(TPB_E) void edge_out_kernel(
    const float* __restrict__ W2, const float* __restrict__ b2,
    float* __restrict__ out, int E, int stride) {
    const int lane = threadIdx.x & 31;
    const int hl = lane & 15;
    const int half = lane >> 4;
    const int gw = blockIdx.x * WPB + (threadIdx.x >> 5);

    // BN affine in half2 (4+4 regs instead of 8+8 fp32)
    __half2 a2[4], c2[4];
    {
        float4 t0 = *(const float4*)&g_a[hl * 8];
        float4 t1 = *(const float4*)&g_a[hl * 8 + 4];
        a2[0] = __floats2half2_rn(t0.x, t0.y);
        a2[1] = __floats2half2_rn(t0.z, t0.w);
        a2[2] = __floats2half2_rn(t1.x, t1.y);
        a2[3] = __floats2half2_rn(t1.z, t1.w);
        t0 = *(const float4*)&g_c[hl * 8];
        t1 = *(const float4*)&g_c[hl * 8 + 4];
        c2[0] = __floats2half2_rn(t0.x, t0.y);
        c2[1] = __floats2half2_rn(t0.z, t0.w);
        c2[2] = __floats2half2_rn(t1.x, t1.y);
        c2[3] = __floats2half2_rn(t1.z, t1.w);
    }
    // W2 rows stay fp32 (precision-critical dot)
    float wa[8], wb[8];
    {
        float4 t0 = *(const float4*)&W2[hl * 8];
        float4 t1 = *(const float4*)&W2[hl * 8 + 4];
        wa[0]=t0.x; wa[1]=t0.y; wa[2]=t0.z; wa[3]=t0.w;
        wa[4]=t1.x; wa[5]=t1.y; wa[6]=t1.z; wa[7]=t1.w;
        t0 = *(const float4*)&W2[128 + hl * 8];
        t1 = *(const float4*)&W2[128 + hl * 8 + 4];
        wb[0]=t0.x; wb[1]=t0.y; wb[2]=t0.z; wb[3]=t0.w;
        wb[4]=t1.x; wb[5]=t1.y; wb[6]=t1.z; wb[7]=t1.w;
    }
    const float bz0 = b2[0], bz1 = b2[1];
    const __half2 z2 = __float2half2_rn(0.f);

    const uint4* __restrict__ U = (const uint4*)g_u;
    const uint4* __restrict__ V = (const uint4*)g_v;
    const int4* __restrict__ EI = (const int4*)g_ei32;

#pragma unroll 4
    for (int it = gw * 2; it < E; it += stride) {
        int4 idx = EI[it >> 1];
        int src = half ? idx.z : idx.x;
        int dst = half ? idx.w : idx.y;
        uint4 ur = U[src * 16 + hl];
        uint4 vr = V[dst * 16 + hl];
        // w = u + v, rr = max(a*w + c, 0): all fp16 (HADD2 + HFMA2 + HMAX2)
        __half2 w01 = __hadd2(*(__half2*)&ur.x, *(__half2*)&vr.x);
        __half2 w23 = __hadd2(*(__half2*)&ur.y, *(__half2*)&vr.y);
        __half2 w45 = __hadd2(*(__half2*)&ur.z, *(__half2*)&vr.z);
        __half2 w67 = __hadd2(*(__half2*)&ur.w, *(__half2*)&vr.w);
        __half2 r01 = __hmax2(__hfma2(a2[0], w01, c2[0]), z2);
        __half2 r23 = __hmax2(__hfma2(a2[1], w23, c2[1]), z2);
        __half2 r45 = __hmax2(__hfma2(a2[2], w45, c2[2]), z2);
        __half2 r67 = __hmax2(__hfma2(a2[3], w67, c2[3]), z2);
        float2 f0 = __half22float2(r01);
        float2 f1 = __half22float2(r23);
        float2 f2 = __half22float2(r45);
        float2 f3 = __half22float2(r67);
        float rr[8] = {f0.x, f0.y, f1.x, f1.y, f2.x, f2.y, f3.x, f3.y};
        float p0 = 0.f, p1 = 0.f;
#pragma unroll
        for (int j = 0; j < 8; j++) {
            p0 = fmaf(rr[j], wa[j], p0);
            p1 = fmaf(rr[j], wb[j], p1);
        }
#pragma unroll
        for (int o = 8; o > 0; o >>= 1) {
            p0 += __shfl_xor_sync(0xFFFFFFFFu, p0, o);
            p1 += __shfl_xor_sync(0xFFFFFFFFu, p1, o);
        }
        if (hl == 0)
            ((float2*)out)[it + half] = make_float2(p0 + bz0, p1 + bz1);
    }
}

// ---------------- launch ------------------------------------------------
extern "C" void kernel_launch(void* const* d_in, const int* in_sizes, int n_in,
                              void* d_out, int out_size) {
    const float* x = (const float*)d_in[0];
    const long long* ei = (const long long*)d_in[1];
    const float* W1 = (const float*)d_in[2];
    // d_in[3] = b1 : cancels inside BatchNorm, unused
    const float* gamma = (const float*)d_in[4];
    const float* beta = (const float*)d_in[5];
    const float* W2 = (const float*)d_in[6];
    const float* b2 = (const float*)d_in[7];

    const int N = in_sizes[0] / DD;
    const int E = in_sizes[1] / 2;
    const int stride = NBLK_E * WPB * 2;
    const int eb = (E + 255) / 256;

    static int smem_set = 0;
    if (!smem_set) {
        cudaFuncSetAttribute(node_gemm_mma_kernel,
                             cudaFuncAttributeMaxDynamicSharedMemorySize, GEMM_SMEM);
        smem_set = 1;
    }

    prep_kernel<<<128 + eb, 256>>>(W1, ei, E);
    node_gemm_mma_kernel<<<(N + 127) / 128, 256, GEMM_SMEM>>>(x, N);
    edge_stats_kernel<<<NBLK_E, TPB_E>>>(E, stride);
    reduce_finalize_kernel<<<128, 256>>>(gamma, beta, 1.0f / (float)E);
    edge_out_kernel<<<NBLK_E, TPB_E>>>(W2, b2, (float*)d_out, E, stride);
}